// round 7
// baseline (speedup 1.0000x reference)
#include <cuda_runtime.h>
#include <cuda_fp16.h>
#include <cstdint>

namespace {
constexpr int B_ = 4, K_ = 4, G_ = 8, W_ = 64, H_ = 64;
constexpr int THREADS = 512;                    // 16 warps = 16 positions per iteration
constexpr int WROW_H = 512;                     // halfs per channel row (32 feat x 16 taps)
constexpr int WHALFS = 64 * WROW_H;             // 32768 halfs = 64 KB
constexpr int SH = 520;                         // stage stride in halfs (260 words = 4 mod 32)
constexpr int CTAS_PER_G = 128;
constexpr int HBLK_PER_CTA = 16;
constexpr int ITERS = 8;                        // two h-blocks (16 positions) per iter
constexpr size_t SMEM_BYTES = (size_t)WHALFS * 2 + (size_t)16 * SH * 2;  // 82176 B

__device__ __forceinline__ unsigned pack_half2(float a, float b) {
    __half2 h = __floats2half2_rn(a, b);
    return *reinterpret_cast<unsigned*>(&h);
}

__global__ void __launch_bounds__(THREADS, 2)
deconv_deindex_kernel(const int* __restrict__ indp, const int* __restrict__ indn,
                      const float* __restrict__ valp, const float* __restrict__ valn,
                      const float* __restrict__ wgt, float* __restrict__ out)
{
    extern __shared__ __half smh[];
    __half* Wh     = smh;                        // [64 ch][512 halfs], quad-swizzled
    __half* stageH = smh + WHALFS;               // [16 pos][520 halfs], quad-swizzled

    const int tid  = threadIdx.x;
    const int lane = tid & 31;
    const int wp   = tid >> 5;

    const int g  = blockIdx.x >> 7;              // 128 CTAs per group
    const int cg = blockIdx.x & 127;

    // Load + convert + swizzle the full group weight slice (64 ch x 512 taps).
    // Quad swizzle: quad q of a row stored at half-offset 8q ^ (((q>>3)&1)<<3).
    {
        const float4* wsrc = reinterpret_cast<const float4*>(wgt) + (size_t)g * 8192;
        #pragma unroll
        for (int i = 0; i < 16; i++) {
            const int idx = i * THREADS + tid;   // 0..8191 float4 chunks
            const int c   = idx >> 7;            // channel
            const int u   = idx & 127;           // float4 (=uint2 of halfs) within row
            float4 v = wsrc[(size_t)c * 128 + u];
            const int off = (4 * u) ^ (((u >> 4) & 1) << 3);  // swizzled half offset
            *reinterpret_cast<uint2*>(Wh + c * WROW_H + off) =
                make_uint2(pack_half2(v.x, v.y), pack_half2(v.z, v.w));
        }
    }
    __syncthreads();

    const int KS = G_ * W_ * H_;                 // k-stride (32768)
    const int swzH = ((lane >> 2) & 1) << 3;     // per-lane quad swizzle (halfs)
    const int lbase = lane * 16;                 // lane's tap base within a row

    for (int it = 0; it < ITERS; it++) {
        const int hpb  = cg * HBLK_PER_CTA + it * 2;   // even h-block index within group
        const int hblk = hpb + (wp >> 3);
        const int hb = hblk & 7;
        const int w  = (hblk >> 3) & 63;
        const int b  = hblk >> 9;
        const int h  = hb * 8 + (wp & 7);

        const int base = (((b * K_) * G_ + g) * W_ + w) * H_ + h;

        // 8 scatter entries (warp-uniform broadcast loads).
        int ind[8];
        #pragma unroll
        for (int k = 0; k < 4; k++) {
            ind[k]     = __ldg(indp + base + k * KS);
            ind[4 + k] = __ldg(indn + base + k * KS);
        }

        // Last-write-wins dedup: entry t survives iff no later entry hits its channel.
        unsigned km = 0xFFu;
        #pragma unroll
        for (int t = 0; t < 7; t++) {
            bool dup = false;
            #pragma unroll
            for (int u = t + 1; u < 8; u++) dup = dup || (ind[u] == ind[t]);
            if (dup) km &= ~(1u << t);
        }

        // Lane owns taps [16*lane, 16*lane+16): two swizzled uint4 LDS per entry.
        __half2 a0 = __float2half2_rn(0.f), a1 = a0, a2 = a0, a3 = a0;
        __half2 a4 = a0, a5 = a0, a6 = a0, a7 = a0;
        #pragma unroll
        for (int t = 0; t < 8; t++) {
            const float* vp = (t < 4) ? (valp + base + t * KS)
                                      : (valn + base + (t - 4) * KS);
            float v = __ldg(vp);
            v = ((km >> t) & 1) ? v : 0.0f;
            const __half2 vv = __float2half2_rn(v);
            const __half* wrow = Wh + ind[t] * WROW_H + lbase;
            uint4 uA = *reinterpret_cast<const uint4*>(wrow + swzH);        // taps +0..7
            uint4 uB = *reinterpret_cast<const uint4*>(wrow + (swzH ^ 8));  // taps +8..15
            a0 = __hfma2(vv, *reinterpret_cast<const __half2*>(&uA.x), a0);
            a1 = __hfma2(vv, *reinterpret_cast<const __half2*>(&uA.y), a1);
            a2 = __hfma2(vv, *reinterpret_cast<const __half2*>(&uA.z), a2);
            a3 = __hfma2(vv, *reinterpret_cast<const __half2*>(&uA.w), a3);
            a4 = __hfma2(vv, *reinterpret_cast<const __half2*>(&uB.x), a4);
            a5 = __hfma2(vv, *reinterpret_cast<const __half2*>(&uB.y), a5);
            a6 = __hfma2(vv, *reinterpret_cast<const __half2*>(&uB.z), a6);
            a7 = __hfma2(vv, *reinterpret_cast<const __half2*>(&uB.w), a7);
        }

        // Stage in fp16 with the same quad swizzle (conflict-free STS.128 x2).
        {
            __half* srow = stageH + wp * SH + lbase;
            uint4 pA, pB;
            pA.x = *reinterpret_cast<unsigned*>(&a0);
            pA.y = *reinterpret_cast<unsigned*>(&a1);
            pA.z = *reinterpret_cast<unsigned*>(&a2);
            pA.w = *reinterpret_cast<unsigned*>(&a3);
            pB.x = *reinterpret_cast<unsigned*>(&a4);
            pB.y = *reinterpret_cast<unsigned*>(&a5);
            pB.z = *reinterpret_cast<unsigned*>(&a6);
            pB.w = *reinterpret_cast<unsigned*>(&a7);
            *reinterpret_cast<uint4*>(srow + swzH)       = pA;
            *reinterpret_cast<uint4*>(srow + (swzH ^ 8)) = pB;
        }
        __syncthreads();

        // Store phase: 1024 chunk-items (16 pos x 64 chunks of 8 taps), 2 per thread.
        {
            const int b2  = hpb >> 9;
            const int w2  = (hpb >> 3) & 63;
            const int hb0 = hpb & 7;                   // even
            float* obase = out + (((size_t)b2 * 256 + g * 32) * 256
                                  + 4 * w2) * 256 + hb0 * 32;
            #pragma unroll
            for (int r = 0; r < 2; r++) {
                const int idx = r * THREADS + tid;     // 0..1023
                const int e = idx & 15;                // position (oh block)
                const int c = idx >> 4;                // tap chunk 0..63
                const int hoff = e * SH + ((8 * c) ^ (((c >> 3) & 1) << 3));
                uint4 u = *reinterpret_cast<const uint4*>(stageH + hoff);
                float2 f0 = __half22float2(*reinterpret_cast<const __half2*>(&u.x));
                float2 f1 = __half22float2(*reinterpret_cast<const __half2*>(&u.y));
                float2 f2 = __half22float2(*reinterpret_cast<const __half2*>(&u.z));
                float2 f3 = __half22float2(*reinterpret_cast<const __half2*>(&u.w));
                const int f  = c >> 1;                 // feature 0..31
                const int i0 = (c & 1) * 2;            // kernel-row pair base
                float* p0 = obase + ((size_t)f * 256 + i0) * 256 + e * 4;
                *reinterpret_cast<float4*>(p0)       = make_float4(f0.x, f0.y, f1.x, f1.y);
                *reinterpret_cast<float4*>(p0 + 256) = make_float4(f2.x, f2.y, f3.x, f3.y);
            }
        }
        __syncthreads();                               // protect stage for next iteration
    }
}
}  // namespace

extern "C" void kernel_launch(void* const* d_in, const int* in_sizes, int n_in,
                              void* d_out, int out_size) {
    const int*   indp = (const int*)d_in[0];
    const int*   indn = (const int*)d_in[1];
    const float* valp = (const float*)d_in[2];
    const float* valn = (const float*)d_in[3];
    const float* wgt  = (const float*)d_in[4];
    float* out = (float*)d_out;

    cudaFuncSetAttribute(deconv_deindex_kernel,
                         cudaFuncAttributeMaxDynamicSharedMemorySize, (int)SMEM_BYTES);
    cudaFuncSetAttribute(deconv_deindex_kernel,
                         cudaFuncAttributePreferredSharedMemoryCarveout, 100);
    deconv_deindex_kernel<<<G_ * CTAS_PER_G, THREADS, SMEM_BYTES>>>(
        indp, indn, valp, valn, wgt, out);
}

// round 9
// speedup vs baseline: 1.2776x; 1.2776x over previous
#include <cuda_runtime.h>
#include <cuda_fp16.h>
#include <cstdint>

namespace {
constexpr int THREADS = 512;
constexpr int CTAS_PER_G = 37;                // 8*37 = 296 = 2 CTAs x 148 SMs
constexpr int TILES_PER_G = 128;              // 16384 positions / 128

// SMEM byte layout
constexpr int SM_X  = 0;                      // X: 128 pos x 64 f16 (128B rows, SW128) = 16KB
constexpr int SM_W  = 16384;                  // W^T: 512 n x 64 f16 (128B rows, SW128) = 64KB
constexpr int SM_ST = 81920;                  // stage: 16 warps x 16 rows x 20 words = 20KB
constexpr int SMEM_TOTAL = 102400;            // -> 2 CTAs/SM
constexpr int ST_STRIDE = 20;                 // stage row stride (words)

__device__ __forceinline__ uint32_t smem_u32(const void* p) {
    uint32_t a;
    asm("{ .reg .u64 t; cvta.to.shared.u64 t, %1; cvt.u32.u64 %0, t; }" : "=r"(a) : "l"(p));
    return a;
}
__device__ __forceinline__ uint32_t sw128(uint32_t b) { return b ^ ((b >> 3) & 0x70); }

__device__ __forceinline__ void ldsm_x4(uint32_t& r0, uint32_t& r1, uint32_t& r2,
                                        uint32_t& r3, uint32_t addr) {
    asm volatile("ldmatrix.sync.aligned.m8n8.x4.shared.b16 {%0,%1,%2,%3}, [%4];"
                 : "=r"(r0), "=r"(r1), "=r"(r2), "=r"(r3) : "r"(addr));
}
__device__ __forceinline__ void mma16816(float& d0, float& d1, float& d2, float& d3,
                                         uint32_t a0, uint32_t a1, uint32_t a2, uint32_t a3,
                                         uint32_t b0, uint32_t b1) {
    asm volatile(
        "mma.sync.aligned.m16n8k16.row.col.f32.f16.f16.f32 "
        "{%0,%1,%2,%3}, {%4,%5,%6,%7}, {%8,%9}, {%0,%1,%2,%3};"
        : "+f"(d0), "+f"(d1), "+f"(d2), "+f"(d3)
        : "r"(a0), "r"(a1), "r"(a2), "r"(a3), "r"(b0), "r"(b1));
}

__global__ void __launch_bounds__(THREADS, 2)
deconv_hmma_kernel(const int* __restrict__ indp, const int* __restrict__ indn,
                   const float* __restrict__ valp, const float* __restrict__ valn,
                   const float* __restrict__ wgt, float* __restrict__ out)
{
    extern __shared__ char smc[];
    const uint32_t sb = smem_u32(smc);

    const int tid  = threadIdx.x;
    const int lane = tid & 31;
    const int wp   = tid >> 5;

    const int g    = blockIdx.x / CTAS_PER_G;
    const int cidx = blockIdx.x % CTAS_PER_G;

    // ---- Build W^T in smem: Wsm[n][c] = (f16) wgt[g*32768 + c*512 + n], SW128 rows.
    {
        const int n = tid;                     // 0..511
        #pragma unroll
        for (int c8 = 0; c8 < 8; c8++) {
            const int c0 = c8 * 8;
            unsigned pk[4];
            #pragma unroll
            for (int q = 0; q < 4; q++) {
                float f0 = __ldg(wgt + (size_t)g * 32768 + (size_t)(c0 + 2*q    ) * 512 + n);
                float f1 = __ldg(wgt + (size_t)g * 32768 + (size_t)(c0 + 2*q + 1) * 512 + n);
                __half2 h = __floats2half2_rn(f0, f1);
                pk[q] = *reinterpret_cast<unsigned*>(&h);
            }
            *reinterpret_cast<uint4*>(smc + SM_W + sw128((uint32_t)n * 128 + c0 * 2)) =
                make_uint4(pk[0], pk[1], pk[2], pk[3]);
        }
    }

    const int s      = wp >> 1;                // m16 stripe 0..7
    const int nhalf  = wp & 1;                 // n half 0..1
    float* St = reinterpret_cast<float*>(smc + SM_ST) + wp * (16 * ST_STRIDE);
    const int KS = 32768;                      // k-stride in scatter tensors

    for (int t = cidx; t < TILES_PER_G; t += CTAS_PER_G) {
        const int bb = t >> 5;                 // batch
        const int w0 = (t & 31) * 2;           // first of two w-rows in this tile

        __syncthreads();                       // protect X (and W on iter 0) before rebuild

        // ---- Build X tile: 128 pos x 64 ch fp16, SW128, program-ordered scatter.
        if (tid < 128) {
            const int pp = tid;
            const int h  = pp & 63;
            const int w  = w0 + (pp >> 6);
            char* xrow = smc + SM_X + pp * 128;
            const uint4 z = make_uint4(0, 0, 0, 0);
            #pragma unroll
            for (int q = 0; q < 8; q++)
                *reinterpret_cast<uint4*>(xrow + q * 16) = z;
            const int base = (((bb * 4) * 8 + g) << 12) + w * 64 + h;
            const uint32_t rsw = ((uint32_t)pp & 7) << 4;
            #pragma unroll
            for (int k = 0; k < 4; k++) {      // pos scatter (k ascending)
                const int    c = __ldg(indp + base + k * KS);
                const __half v = __float2half(__ldg(valp + base + k * KS));
                *reinterpret_cast<__half*>(xrow + (((uint32_t)(2 * c)) ^ rsw)) = v;
            }
            #pragma unroll
            for (int k = 0; k < 4; k++) {      // neg scatter overwrites pos
                const int    c = __ldg(indn + base + k * KS);
                const __half v = __float2half(__ldg(valn + base + k * KS));
                *reinterpret_cast<__half*>(xrow + (((uint32_t)(2 * c)) ^ rsw)) = v;
            }
        }
        __syncthreads();

        // ---- A fragments: m16k64 for this stripe (4 k-chunks of 16).
        uint32_t a[4][4];
        {
            const int arow = 16 * s + (lane & 15);
            const int acol = (lane >> 4) * 16;       // byte offset of 8-half k block
            #pragma unroll
            for (int kc = 0; kc < 4; kc++) {
                const uint32_t addr =
                    sb + SM_X + sw128((uint32_t)arow * 128 + kc * 32 + acol);
                ldsm_x4(a[kc][0], a[kc][1], a[kc][2], a[kc][3], addr);
            }
        }

        // Output geometry for this warp
        const int wo  = w0 + (s >> 2);
        const int h0  = 16 * (s & 3);
        const int nr  = lane & 7;              // B ldmatrix row within n8
        const int jm  = lane >> 3;             // B ldmatrix matrix index 0..3

        #pragma unroll 1
        for (int nb = 0; nb < 16; nb++) {
            const int f = nhalf * 16 + nb;     // feature (16 taps = this n16 batch)

            float d0 = 0.f, d1 = 0.f, d2 = 0.f, d3 = 0.f;   // tile0: taps 0..7
            float d4 = 0.f, d5 = 0.f, d6 = 0.f, d7 = 0.f;   // tile1: taps 8..15
            const int nrow = f * 16 + (jm >> 1) * 8 + nr;   // W^T row for this lane
            const int kb   = (jm & 1) * 16;                  // byte offset (k 0-7 / 8-15)
            #pragma unroll
            for (int kc = 0; kc < 4; kc++) {
                uint32_t b0, b1, b2, b3;
                const uint32_t addr =
                    sb + SM_W + sw128((uint32_t)nrow * 128 + kc * 32 + kb);
                ldsm_x4(b0, b1, b2, b3, addr);
                mma16816(d0, d1, d2, d3, a[kc][0], a[kc][1], a[kc][2], a[kc][3], b0, b1);
                mma16816(d4, d5, d6, d7, a[kc][0], a[kc][1], a[kc][2], a[kc][3], b2, b3);
            }

            // ---- Stage (warp-private): stage[row=pos][col=tap 0..15], stride 20.
            {
                const int r = lane >> 2, q = lane & 3;
                *reinterpret_cast<float2*>(St + r * ST_STRIDE + 2 * q)            = make_float2(d0, d1);
                *reinterpret_cast<float2*>(St + (r + 8) * ST_STRIDE + 2 * q)      = make_float2(d2, d3);
                *reinterpret_cast<float2*>(St + r * ST_STRIDE + 2 * q + 8)        = make_float2(d4, d5);
                *reinterpret_cast<float2*>(St + (r + 8) * ST_STRIDE + 2 * q + 8)  = make_float2(d6, d7);
            }
            __syncwarp();

            // ---- Coalesced store: 64 float4s = 4 runs of 256B (one per kernel-row i).
            {
                float* obase = out + (((size_t)(bb * 256 + g * 32 + f)) * 256
                                      + 4 * wo) * 256 + 4 * h0;
                #pragma unroll
                for (int z = 0; z < 2; z++) {
                    const int idx = z * 32 + lane;   // 0..63
                    const int i   = idx >> 4;        // kernel row 0..3
                    const int hh  = idx & 15;        // position within stripe
                    const float4 vv = *reinterpret_cast<const float4*>(
                        St + hh * ST_STRIDE + 4 * i);
                    *reinterpret_cast<float4*>(obase + (size_t)i * 256 + 4 * hh) = vv;
                }
            }
            __syncwarp();                      // protect stage before next batch
        }
    }
}
}  // namespace

extern "C" void kernel_launch(void* const* d_in, const int* in_sizes, int n_in,
                              void* d_out, int out_size) {
    const int*   indp = (const int*)d_in[0];
    const int*   indn = (const int*)d_in[1];
    const float* valp = (const float*)d_in[2];
    const float* valn = (const float*)d_in[3];
    const float* wgt  = (const float*)d_in[4];
    float* out = (float*)d_out;

    cudaFuncSetAttribute(deconv_hmma_kernel,
                         cudaFuncAttributeMaxDynamicSharedMemorySize, SMEM_TOTAL);
    cudaFuncSetAttribute(deconv_hmma_kernel,
                         cudaFuncAttributePreferredSharedMemoryCarveout, 100);
    deconv_hmma_kernel<<<8 * CTAS_PER_G, THREADS, SMEM_TOTAL>>>(
        indp, indn, valp, valn, wgt, out);
}